// round 1
// baseline (speedup 1.0000x reference)
#include <cuda_runtime.h>
#include <math.h>

#define BB 2048
#define KK 20
#define DD 128
#define TT 100
#define CC 128
#define TKN 40
#define HT 20
#define HC 512

// Scratch (device globals; no runtime allocation allowed)
__device__ float g_tok [(size_t)BB * TKN * CC];
__device__ float g_tok2[(size_t)BB * TKN * CC];

// Packed fp32x2 FMA (Blackwell FFMA2; only reachable via PTX fma.rn.f32x2)
__device__ __forceinline__ float2 ffma2(float2 a, float2 b, float2 c) {
    float2 d;
    asm("fma.rn.f32x2 %0, %1, %2, %3;"
        : "=l"(*reinterpret_cast<unsigned long long*>(&d))
        : "l"(*reinterpret_cast<unsigned long long*>(&a)),
          "l"(*reinterpret_cast<unsigned long long*>(&b)),
          "l"(*reinterpret_cast<unsigned long long*>(&c)));
    return d;
}

__device__ __forceinline__ float gelu_(float x) {
    return 0.5f * x * (1.f + erff(x * 0.7071067811865476f));
}

// ---------------------------------------------------------------------------
// One-hop branch: tokens[b,t,:] = concat(edge_table[eid], tenc(dt,eid)) @ proj_W + b
// 2 rows per 128-thread block; 64 threads per row, each owns a float2 of outputs.
// ---------------------------------------------------------------------------
__global__ __launch_bounds__(128) void k_onehop(
    const float* __restrict__ et,
    const int*   __restrict__ srcI, const int* __restrict__ dstI,
    const float* __restrict__ dts,  const float* __restrict__ dtd,
    const float* __restrict__ tw,   const float* __restrict__ tbv,
    const float* __restrict__ W,    const float* __restrict__ bias)
{
    __shared__ float feat[2][232];
    const int half = threadIdx.x >> 6;
    const int lane = threadIdx.x & 63;
    const int row  = blockIdx.x * 2 + half;
    const int b = row / TKN, t = row % TKN;

    int eid; float dt;
    if (t < KK) { eid = srcI[b*KK + t];        dt = dts[b*KK + t]; }
    else        { eid = dstI[b*KK + t - KK];   dt = dtd[b*KK + t - KK]; }

    const float* er = et + (size_t)eid * DD;
    feat[half][lane]      = er[lane];
    feat[half][lane + 64] = er[lane + 64];
    const float msk = (eid == 0) ? 0.f : 1.f;
    feat[half][DD + lane] = msk * cosf(dt * tw[lane] + tbv[lane]);
    if (lane < TT - 64)
        feat[half][DD + 64 + lane] = msk * cosf(dt * tw[64 + lane] + tbv[64 + lane]);
    __syncthreads();

    const int c0 = lane * 2;
    float2 acc = *(const float2*)&bias[c0];
    const float* fp = feat[half];
    #pragma unroll 4
    for (int f = 0; f < DD + TT; ++f) {
        float2 w = *(const float2*)&W[f * CC + c0];
        float a = fp[f];
        acc = ffma2(make_float2(a, a), w, acc);
    }
    *(float2*)&g_tok[((size_t)b * TKN + t) * CC + c0] = acc;
}

// ---------------------------------------------------------------------------
// Two-hop branch: feat = [e1 | e2 | e | tenc(dt2, e1)] (484) @ eproj_W[j] + eproj_b[j]
// ---------------------------------------------------------------------------
__global__ __launch_bounds__(128) void k_twohop(
    const float* __restrict__ et,
    const int* __restrict__ srcI, const int* __restrict__ dstI,
    const int* __restrict__ s2e1, const int* __restrict__ s2e2,
    const int* __restrict__ d2e1, const int* __restrict__ d2e2,
    const float* __restrict__ dt2s, const float* __restrict__ dt2d,
    const float* __restrict__ tw,   const float* __restrict__ tbv,
    const float* __restrict__ eW,   const float* __restrict__ eb)
{
    __shared__ float feat[2][488];
    const int half = threadIdx.x >> 6;
    const int lane = threadIdx.x & 63;
    const int row  = blockIdx.x * 2 + half;
    const int b = row / TKN, t = row % TKN;

    int e1, e2, e3, j; float dt;
    if (t < KK) { int i = b*KK + t;      e1 = s2e1[i]; e2 = s2e2[i]; e3 = srcI[i]; dt = dt2s[i]; j = 0; }
    else        { int i = b*KK + t - KK; e1 = d2e1[i]; e2 = d2e2[i]; e3 = dstI[i]; dt = dt2d[i]; j = 1; }

    const float* r1 = et + (size_t)e1 * DD;
    const float* r2 = et + (size_t)e2 * DD;
    const float* r3 = et + (size_t)e3 * DD;
    feat[half][lane]            = r1[lane];
    feat[half][lane + 64]       = r1[lane + 64];
    feat[half][128 + lane]      = r2[lane];
    feat[half][128 + lane + 64] = r2[lane + 64];
    feat[half][256 + lane]      = r3[lane];
    feat[half][256 + lane + 64] = r3[lane + 64];
    const float msk = (e1 == 0) ? 0.f : 1.f;
    feat[half][384 + lane] = msk * cosf(dt * tw[lane] + tbv[lane]);
    if (lane < TT - 64)
        feat[half][384 + 64 + lane] = msk * cosf(dt * tw[64 + lane] + tbv[64 + lane]);
    __syncthreads();

    const int F = 3 * DD + TT;  // 484
    const float* W = eW + (size_t)j * F * CC;
    const int c0 = lane * 2;
    float2 acc = *(const float2*)&eb[j * CC + c0];
    const float* fp = feat[half];
    #pragma unroll 4
    for (int f = 0; f < F; ++f) {
        float2 w = *(const float2*)&W[f * CC + c0];
        float a = fp[f];
        acc = ffma2(make_float2(a, a), w, acc);
    }
    *(float2*)&g_tok2[((size_t)b * TKN + t) * CC + c0] = acc;
}

// ---------------------------------------------------------------------------
// Mixer layer: one CTA per sample, all state in shared memory.
// token-mix (LN over 40 + FFN 40->20->40) then channel-mix (LN over 128 + FFN 128->512->128)
// ---------------------------------------------------------------------------
struct MixS {
    float x[TKN][CC];       // 20480 B
    float xln[TKN][CC];     // 20480 B
    float h[TKN][HC];       // 81920 B
    float tw1[TKN * HT];
    float tw2[HT * TKN];
    float tb1[HT], tb2[TKN], tg[TKN], tb[TKN];
    float cg[CC], cb[CC];
    float cb1[HC], cb2[CC];
};

__global__ __launch_bounds__(256, 1) void k_mixer(
    int which, int mi,
    const float* __restrict__ tlng, const float* __restrict__ tlnb,
    const float* __restrict__ tW1,  const float* __restrict__ tB1,
    const float* __restrict__ tW2,  const float* __restrict__ tB2,
    const float* __restrict__ clng, const float* __restrict__ clnb,
    const float* __restrict__ cW1,  const float* __restrict__ cB1,
    const float* __restrict__ cW2,  const float* __restrict__ cB2)
{
    extern __shared__ char raw[];
    MixS& s = *reinterpret_cast<MixS*>(raw);
    const int tid = threadIdx.x;
    float* xg = (which ? g_tok2 : g_tok) + (size_t)blockIdx.x * TKN * CC;

    for (int i = tid; i < TKN * CC / 4; i += 256)
        ((float4*)s.x)[i] = ((const float4*)xg)[i];
    for (int i = tid; i < TKN * HT; i += 256) s.tw1[i] = tW1[mi * TKN * HT + i];
    for (int i = tid; i < HT * TKN; i += 256) s.tw2[i] = tW2[mi * HT * TKN + i];
    for (int i = tid; i < HC; i += 256)       s.cb1[i] = cB1[mi * HC + i];
    if (tid < HT)  s.tb1[tid] = tB1[mi * HT + tid];
    if (tid < TKN) { s.tb2[tid] = tB2[mi*TKN+tid]; s.tg[tid] = tlng[mi*TKN+tid]; s.tb[tid] = tlnb[mi*TKN+tid]; }
    if (tid < CC)  { s.cg[tid] = clng[mi*CC+tid];  s.cb[tid] = clnb[mi*CC+tid];  s.cb2[tid] = cB2[mi*CC+tid]; }
    __syncthreads();

    // ---- token mixing: thread c handles channel c ----
    if (tid < CC) {
        const int c = tid;
        float v[TKN];
        float sum = 0.f;
        #pragma unroll
        for (int t = 0; t < TKN; ++t) { v[t] = s.x[t][c]; sum += v[t]; }
        const float mean = sum * (1.f / TKN);
        float var = 0.f;
        #pragma unroll
        for (int t = 0; t < TKN; ++t) { float d = v[t] - mean; var += d * d; }
        const float rstd = rsqrtf(var * (1.f / TKN) + 1e-5f);
        float h1[HT];
        #pragma unroll
        for (int j = 0; j < HT; ++j) h1[j] = s.tb1[j];
        #pragma unroll
        for (int t = 0; t < TKN; ++t) {
            float a = (v[t] - mean) * rstd * s.tg[t] + s.tb[t];
            #pragma unroll
            for (int j = 0; j < HT; ++j) h1[j] += a * s.tw1[t * HT + j];
        }
        #pragma unroll
        for (int j = 0; j < HT; ++j) h1[j] = gelu_(h1[j]);
        #pragma unroll
        for (int t = 0; t < TKN; ++t) {
            float o = s.tb2[t];
            #pragma unroll
            for (int j = 0; j < HT; ++j) o += h1[j] * s.tw2[j * TKN + t];
            s.x[t][c] = v[t] + o;
        }
    }
    __syncthreads();

    // ---- channel LN -> xln (warp per token) ----
    {
        const int w = tid >> 5, ln = tid & 31;
        for (int t = w; t < TKN; t += 8) {
            float4 xv = *(const float4*)&s.x[t][ln * 4];
            float ssum = xv.x + xv.y + xv.z + xv.w;
            #pragma unroll
            for (int o = 16; o > 0; o >>= 1) ssum += __shfl_xor_sync(0xffffffffu, ssum, o);
            const float mean = ssum * (1.f / CC);
            float dx = xv.x - mean, dy = xv.y - mean, dz = xv.z - mean, dw = xv.w - mean;
            float vs = dx*dx + dy*dy + dz*dz + dw*dw;
            #pragma unroll
            for (int o = 16; o > 0; o >>= 1) vs += __shfl_xor_sync(0xffffffffu, vs, o);
            const float rstd = rsqrtf(vs * (1.f / CC) + 1e-5f);
            const int c = ln * 4;
            float4 out;
            out.x = dx * rstd * s.cg[c+0] + s.cb[c+0];
            out.y = dy * rstd * s.cg[c+1] + s.cb[c+1];
            out.z = dz * rstd * s.cg[c+2] + s.cb[c+2];
            out.w = dw * rstd * s.cg[c+3] + s.cb[c+3];
            *(float4*)&s.xln[t][c] = out;
        }
    }
    __syncthreads();

    // ---- GEMM1: h = gelu(xln[40,128] @ cW1[128,512] + cb1) ----
    // thread owns 4 j-columns (2 f32x2) x 20 tokens; FFMA2:LDS = 2:1
    {
        const int jq = tid & 127, th = tid >> 7;
        const int j0 = jq * 4, t0 = th * 20;
        const float* Wp = cW1 + (size_t)mi * CC * HC;
        float2 a0[20], a1[20];
        const float2 b01 = make_float2(s.cb1[j0],     s.cb1[j0 + 1]);
        const float2 b23 = make_float2(s.cb1[j0 + 2], s.cb1[j0 + 3]);
        #pragma unroll
        for (int t = 0; t < 20; ++t) { a0[t] = b01; a1[t] = b23; }
        #pragma unroll 2
        for (int c = 0; c < CC; ++c) {
            float4 w = *(const float4*)&Wp[(size_t)c * HC + j0];
            float2 w01 = make_float2(w.x, w.y), w23 = make_float2(w.z, w.w);
            #pragma unroll
            for (int t = 0; t < 20; ++t) {
                float a = s.xln[t0 + t][c];
                float2 ad = make_float2(a, a);
                a0[t] = ffma2(ad, w01, a0[t]);
                a1[t] = ffma2(ad, w23, a1[t]);
            }
        }
        #pragma unroll
        for (int t = 0; t < 20; ++t) {
            float4 o;
            o.x = gelu_(a0[t].x); o.y = gelu_(a0[t].y);
            o.z = gelu_(a1[t].x); o.w = gelu_(a1[t].y);
            *(float4*)&s.h[t0 + t][j0] = o;
        }
    }
    __syncthreads();

    // ---- GEMM2: x += h[40,512] @ cW2[512,128] + cb2 ----
    // thread owns 4 c-columns x 5 tokens; FFMA2:LDS = 2:1
    {
        const int cq = tid & 31, tg = tid >> 5;
        const int c0 = cq * 4, t0 = tg * 5;
        const float* Wp = cW2 + (size_t)mi * HC * CC;
        float2 a0[5], a1[5];
        const float2 b01 = make_float2(s.cb2[c0],     s.cb2[c0 + 1]);
        const float2 b23 = make_float2(s.cb2[c0 + 2], s.cb2[c0 + 3]);
        #pragma unroll
        for (int t = 0; t < 5; ++t) { a0[t] = b01; a1[t] = b23; }
        #pragma unroll 4
        for (int j = 0; j < HC; ++j) {
            float4 w = *(const float4*)&Wp[(size_t)j * CC + c0];
            float2 w01 = make_float2(w.x, w.y), w23 = make_float2(w.z, w.w);
            #pragma unroll
            for (int t = 0; t < 5; ++t) {
                float a = s.h[t0 + t][j];
                float2 ad = make_float2(a, a);
                a0[t] = ffma2(ad, w01, a0[t]);
                a1[t] = ffma2(ad, w23, a1[t]);
            }
        }
        #pragma unroll
        for (int t = 0; t < 5; ++t) {
            float4 xv = *(const float4*)&s.x[t0 + t][c0];
            xv.x += a0[t].x; xv.y += a0[t].y; xv.z += a1[t].x; xv.w += a1[t].y;
            *(float4*)&s.x[t0 + t][c0] = xv;
        }
    }
    __syncthreads();

    for (int i = tid; i < TKN * CC / 4; i += 256)
        ((float4*)xg)[i] = ((const float4*)s.x)[i];
}

// ---------------------------------------------------------------------------
// Mean over tokens + pcc-softmax combine
// ---------------------------------------------------------------------------
__global__ __launch_bounds__(128) void k_comb(
    const float* __restrict__ p1, const float* __restrict__ p2, float* __restrict__ out)
{
    const int b = blockIdx.x, c = threadIdx.x;
    const float* t1 = g_tok  + (size_t)b * TKN * CC + c;
    const float* t2 = g_tok2 + (size_t)b * TKN * CC + c;
    float s1 = 0.f, s2 = 0.f;
    #pragma unroll
    for (int t = 0; t < TKN; ++t) { s1 += t1[(size_t)t * CC]; s2 += t2[(size_t)t * CC]; }
    s1 *= (1.f / TKN); s2 *= (1.f / TKN);
    const float a = p1[b], bb = p2[b];
    const float mx = fmaxf(a, bb);
    const float e1 = expf(a - mx), e2 = expf(bb - mx);
    out[(size_t)b * CC + c] = (e1 * s1 + e2 * s2) / (e1 + e2);
}

// ---------------------------------------------------------------------------
extern "C" void kernel_launch(void* const* d_in, const int* in_sizes, int n_in,
                              void* d_out, int out_size)
{
    (void)in_sizes; (void)n_in; (void)out_size;
    const float* et   = (const float*)d_in[0];
    const int*   srcI = (const int*)d_in[1];
    const int*   dstI = (const int*)d_in[2];
    const int*   s2e1 = (const int*)d_in[3];
    const int*   s2e2 = (const int*)d_in[4];
    const int*   d2e1 = (const int*)d_in[5];
    const int*   d2e2 = (const int*)d_in[6];
    const float* dts  = (const float*)d_in[7];
    const float* dtd  = (const float*)d_in[8];
    const float* dt2s = (const float*)d_in[9];
    const float* dt2d = (const float*)d_in[10];
    const float* pcc1 = (const float*)d_in[11];
    const float* pcc2 = (const float*)d_in[12];
    const float* tw   = (const float*)d_in[13];
    const float* tb   = (const float*)d_in[14];
    const float* pW   = (const float*)d_in[15];
    const float* pB   = (const float*)d_in[16];
    const float* eW   = (const float*)d_in[17];
    const float* eB   = (const float*)d_in[18];
    const float* tlng = (const float*)d_in[19];
    const float* tlnb = (const float*)d_in[20];
    const float* tW1  = (const float*)d_in[21];
    const float* tB1  = (const float*)d_in[22];
    const float* tW2  = (const float*)d_in[23];
    const float* tB2  = (const float*)d_in[24];
    const float* clng = (const float*)d_in[25];
    const float* clnb = (const float*)d_in[26];
    const float* cW1  = (const float*)d_in[27];
    const float* cB1  = (const float*)d_in[28];
    const float* cW2  = (const float*)d_in[29];
    const float* cB2  = (const float*)d_in[30];
    float* out = (float*)d_out;

    cudaFuncSetAttribute(k_mixer, cudaFuncAttributeMaxDynamicSharedMemorySize, (int)sizeof(MixS));

    k_onehop<<<BB * TKN / 2, 128>>>(et, srcI, dstI, dts, dtd, tw, tb, pW, pB);
    k_twohop<<<BB * TKN / 2, 128>>>(et, srcI, dstI, s2e1, s2e2, d2e1, d2e2, dt2s, dt2d, tw, tb, eW, eB);
    for (int i = 0; i < 2; ++i)
        k_mixer<<<BB, 256, (int)sizeof(MixS)>>>(0, i,     tlng, tlnb, tW1, tB1, tW2, tB2, clng, clnb, cW1, cB1, cW2, cB2);
    for (int i = 0; i < 2; ++i)
        k_mixer<<<BB, 256, (int)sizeof(MixS)>>>(1, 2 + i, tlng, tlnb, tW1, tB1, tW2, tB2, clng, clnb, cW1, cB1, cW2, cB2);
    k_comb<<<BB, 128>>>(pcc1, pcc2, out);
}